// round 7
// baseline (speedup 1.0000x reference)
#include <cuda_runtime.h>
#include <stdint.h>

#define X_COORD_START 10
#define Y_COORD_START 21
#define EOS_TOKEN     39
#define MAX_REACH     5.0f
#define WINDOW_SIZE   4
#define PENALTY_SCALE 1.0f

#define ROW_LEN      2048   // tokens per row
#define ROWS_PER_CTA 2
#define NTHREADS     128    // 4 warps cooperate per row
#define WCHUNKS      4      // int4 chunks per warp per row

// Self-resetting scratch (zero at module load; last CTA resets after each
// launch so every graph replay starts from zero — deterministic).
__device__ double        g_total   = 0.0;
__device__ int           g_nvs     = 0;
__device__ unsigned int  g_counter = 0;

__device__ __forceinline__ bool is_valid(int x, int y) {
    return ((unsigned)(x - X_COORD_START) < (unsigned)(Y_COORD_START - X_COORD_START)) &
           ((unsigned)(y - Y_COORD_START) < (unsigned)(EOS_TOKEN - Y_COORD_START));
}

__global__ __launch_bounds__(NTHREADS, 7)
void reach_loss_cp(const int* __restrict__ in, float* __restrict__ out,
                   int n_ctas) {
    const int t    = threadIdx.x;
    const int lane = t & 31;
    const int wid  = t >> 5;          // 0..3
    const unsigned lt = (1u << lane) - 1u;

    __shared__ int raw[ROWS_PER_CTA][ROW_LEN];   // 16 KB staged rows
    __shared__ int buf[1024];                    // compacted packed coords
    __shared__ int scnt[4];

    const size_t g0 = (size_t)blockIdx.x * ROWS_PER_CTA * ROW_LEN;
    const unsigned raw_base = (unsigned)__cvta_generic_to_shared(&raw[0][0]);

    // ---- Prefetch both rows via cp.async (no register payload) ----
    #pragma unroll
    for (int r = 0; r < ROWS_PER_CTA; r++) {
        #pragma unroll
        for (int c = 0; c < WCHUNKS; c++) {
            const int q = (wid * WCHUNKS + c) * 32 + lane;   // int4 index
            const unsigned dst = raw_base + (unsigned)(r * ROW_LEN * 4 + q * 16);
            const int* src = in + g0 + (size_t)r * ROW_LEN + 4 * q;
            asm volatile("cp.async.cg.shared.global [%0], [%1], 16;\n"
                         :: "r"(dst), "l"(src));
        }
        asm volatile("cp.async.commit_group;\n");
    }

    double wacc = 0.0;   // per-warp (lane 0) accumulated normalized penalty
    int    wnvs = 0;     // warp 0 lane 0 only

    #pragma unroll
    for (int r = 0; r < ROWS_PER_CTA; r++) {
        if (r == 0) asm volatile("cp.async.wait_group 1;\n");
        else        asm volatile("cp.async.wait_group 0;\n");
        __syncthreads();   // row r staged; also fences prior row's buf reads

        const int4* raw4 = reinterpret_cast<const int4*>(raw[r]);

        // ---- Pass 1: ballots + per-warp counts (ballots live in regs) ----
        // int4 q holds pair A = 2q-1 (tokens 4q,4q+1; q>=1) and pair B = 2q.
        unsigned bA[WCHUNKS], bB[WCHUNKS];
        int cntc[WCHUNKS];
        int cnt = 0;
        #pragma unroll
        for (int c = 0; c < WCHUNKS; c++) {
            const int q = (wid * WCHUNKS + c) * 32 + lane;
            const int4 p = raw4[q];
            const bool va = (q != 0) && is_valid(p.x, p.y);
            const bool vb = is_valid(p.z, p.w);
            bA[c] = __ballot_sync(0xffffffffu, va);
            bB[c] = __ballot_sync(0xffffffffu, vb);
            cntc[c] = cnt;
            cnt += __popc(bA[c]) + __popc(bB[c]);
        }
        if (lane == 0) scnt[wid] = cnt;
        __syncthreads();

        int base = 0;
        #pragma unroll
        for (int w = 0; w < 4; w++) base += (w < wid) ? scnt[w] : 0;
        const int total = scnt[0] + scnt[1] + scnt[2] + scnt[3];

        // ---- Pass 2: stable scatter into contiguous buffer ----
        #pragma unroll
        for (int c = 0; c < WCHUNKS; c++) {
            const int q = (wid * WCHUNKS + c) * 32 + lane;
            const int4 p = raw4[q];
            const int fa = (bA[c] >> lane) & 1;
            const int fb = (bB[c] >> lane) & 1;
            const int pos = base + cntc[c] + __popc(bA[c] & lt) + __popc(bB[c] & lt);
            if (fa) buf[pos]      = (p.y << 16) | p.x;
            if (fb) buf[pos + fa] = (p.w << 16) | p.z;
        }
        __syncthreads();

        // ---- Windowed min sq-distance (integer), one sqrt per element ----
        float vsum = 0.0f;
        for (int i = WINDOW_SIZE + t; i < total; i += NTHREADS) {
            const int pki = buf[i];
            const int xi = pki & 0xffff;
            const int yi = pki >> 16;
            int msq = 0x7fffffff;
            #pragma unroll
            for (int j = 1; j <= WINDOW_SIZE; j++) {
                const int pkj = buf[i - j];
                const int dx = xi - (pkj & 0xffff);
                const int dy = yi - (pkj >> 16);
                msq = min(msq, dx * dx + dy * dy);
            }
            // exact 0 for msq <= 25 (incl. msq == 0)
            vsum += fmaxf(sqrtf((float)msq) - MAX_REACH, 0.0f);
        }
        #pragma unroll
        for (int o = 16; o > 0; o >>= 1)
            vsum += __shfl_xor_sync(0xffffffffu, vsum, o);

        if (total >= WINDOW_SIZE + 1) {
            if (lane == 0)
                wacc += (double)(vsum / (float)(total - WINDOW_SIZE));
            if (t == 0) wnvs += 1;
        }
        // next iteration's first __syncthreads fences buf/scnt reuse
    }

    // ---- Per-warp atomic; last CTA finalizes + resets scratch ----
    if (lane == 0 && wacc != 0.0) atomicAdd(&g_total, wacc);
    if (t == 0 && wnvs)           atomicAdd(&g_nvs, wnvs);
    __syncthreads();
    if (t == 0) {
        __threadfence();
        const unsigned ticket = atomicAdd(&g_counter, 1u);
        if (ticket == (unsigned)(n_ctas - 1)) {
            const double tot = *((volatile double*)&g_total);
            const int    tn  = *((volatile int*)&g_nvs);
            out[0] = (tn > 0) ? (float)(PENALTY_SCALE * tot / (double)tn) : 0.0f;
            g_total = 0.0;
            g_nvs   = 0;
            __threadfence();
            g_counter = 0u;
        }
    }
}

extern "C" void kernel_launch(void* const* d_in, const int* in_sizes, int n_in,
                              void* d_out, int out_size) {
    const int* in = (const int*)d_in[0];
    const int B = in_sizes[0] / ROW_LEN;            // 2048 rows
    const int n_ctas = B / ROWS_PER_CTA;            // 1024 CTAs — one wave
    reach_loss_cp<<<n_ctas, NTHREADS>>>(in, (float*)d_out, n_ctas);
}

// round 8
// speedup vs baseline: 1.3395x; 1.3395x over previous
#include <cuda_runtime.h>
#include <stdint.h>

#define X_COORD_START 10
#define Y_COORD_START 21
#define EOS_TOKEN     39
#define MAX_REACH     5.0f
#define WINDOW_SIZE   4
#define PENALTY_SCALE 1.0f

#define ROW_LEN      2048   // tokens per row
#define ROWS_PER_CTA 2
#define NTHREADS     128    // 4 warps per CTA, all on one row at a time
#define WCHUNKS      4      // int4 chunks per warp per row
#define SEGSTRIDE    260    // 4 halo slots + up to 256 compacted pairs

// Self-resetting scratch (zero at module load; last CTA resets after each
// launch so every graph replay starts from zero — deterministic).
__device__ double        g_total   = 0.0;
__device__ int           g_nvs     = 0;
__device__ unsigned int  g_counter = 0;

__device__ __forceinline__ bool is_valid(int x, int y) {
    return ((unsigned)(x - X_COORD_START) < (unsigned)(Y_COORD_START - X_COORD_START)) &
           ((unsigned)(y - Y_COORD_START) < (unsigned)(EOS_TOKEN - Y_COORD_START));
}

__global__ __launch_bounds__(NTHREADS, 7)
void reach_loss_halo(const int* __restrict__ in, float* __restrict__ out,
                     int n_ctas) {
    const int t    = threadIdx.x;
    const int lane = t & 31;
    const int wid  = t >> 5;          // 0..3
    const unsigned lt = (1u << lane) - 1u;

    __shared__ int   seg[4 * SEGSTRIDE];  // warp-private compacted segments
    __shared__ int   scnt[4];
    __shared__ float wpart[4];

    const int row0 = blockIdx.x * ROWS_PER_CTA;

    // Prologue: load row 0 (warp w covers int4 indices (w*4+c)*32+lane)
    int4 v[WCHUNKS];
    #pragma unroll
    for (int c = 0; c < WCHUNKS; c++)
        v[c] = reinterpret_cast<const int4*>(in + (size_t)row0 * ROW_LEN)
                   [(wid * WCHUNKS + c) * 32 + lane];

    float wacc = 0.0f;   // lane 0 of each warp: sum of normalized penalties
    int   nvs  = 0;      // thread 0 only

    #pragma unroll
    for (int r = 0; r < ROWS_PER_CTA; r++) {
        // ---- Single-pass ballot compaction into warp-private segment ----
        // int4 q holds pair A = 2q-1 (tokens 4q,4q+1; q>=1) and pair B = 2q.
        int* myseg = &seg[wid * SEGSTRIDE];
        int cnt = 0;
        #pragma unroll
        for (int c = 0; c < WCHUNKS; c++) {
            const int4 p = v[c];
            const int q = (wid * WCHUNKS + c) * 32 + lane;
            const bool va = (q != 0) && is_valid(p.x, p.y);
            const bool vb = is_valid(p.z, p.w);
            const unsigned bA = __ballot_sync(0xffffffffu, va);
            const unsigned bB = __ballot_sync(0xffffffffu, vb);
            const int pos = cnt + __popc(bA & lt) + __popc(bB & lt);
            if (va) myseg[4 + pos]              = (p.y << 16) | p.x;
            if (vb) myseg[4 + pos + (va?1:0)]   = (p.w << 16) | p.z;
            cnt += __popc(bA) + __popc(bB);
        }
        if (lane == 0) scnt[wid] = cnt;

        // v consumed: issue next row's loads now (latency hides under
        // barrier + halo + window of this row).
        if (r + 1 < ROWS_PER_CTA) {
            #pragma unroll
            for (int c = 0; c < WCHUNKS; c++)
                v[c] = reinterpret_cast<const int4*>(
                           in + (size_t)(row0 + r + 1) * ROW_LEN)
                           [(wid * WCHUNKS + c) * 32 + lane];
        }
        __syncthreads();

        const int s0 = scnt[0], s1 = scnt[1], s2 = scnt[2], s3 = scnt[3];
        const int prefix = (wid > 0 ? s0 : 0) + (wid > 1 ? s1 : 0)
                         + (wid > 2 ? s2 : 0);
        const int total = s0 + s1 + s2 + s3;

        // ---- Halo fill: lanes 0..3 fetch the 4 global predecessors that
        //      precede this warp's segment, into slots 3-lane (= 4 - k) ----
        if (lane < 4) {
            const int gb = prefix - 1 - lane;   // global compacted index
            if (gb >= 0) {
                int w2, loc;
                if      (gb >= s0 + s1 + s2) { w2 = 3; loc = gb - (s0+s1+s2); }
                else if (gb >= s0 + s1)      { w2 = 2; loc = gb - (s0+s1); }
                else if (gb >= s0)           { w2 = 1; loc = gb - s0; }
                else                         { w2 = 0; loc = gb; }
                myseg[3 - lane] = seg[w2 * SEGSTRIDE + 4 + loc];
            }
        }
        __syncwarp();

        // ---- Uniform window loop over this warp's local pairs ----
        const int* s = myseg + 4;
        const int st = (4 - prefix) > 0 ? (4 - prefix) : 0;  // global>=4 filter
        float vsum = 0.0f;
        for (int i = st + lane; i < cnt; i += 32) {
            const int pki = s[i];
            const int xi = pki & 0xffff;
            const int yi = pki >> 16;
            int msq = 0x7fffffff;
            #pragma unroll
            for (int j = 1; j <= WINDOW_SIZE; j++) {
                const int pkj = s[i - j];           // halo covers i-j < 0..3
                const int dx = xi - (pkj & 0xffff);
                const int dy = yi - (pkj >> 16);
                msq = min(msq, dx * dx + dy * dy);
            }
            // exact 0 for msq <= 25 (incl. msq == 0)
            vsum += fmaxf(sqrtf((float)msq) - MAX_REACH, 0.0f);
        }
        #pragma unroll
        for (int o = 16; o > 0; o >>= 1)
            vsum += __shfl_xor_sync(0xffffffffu, vsum, o);

        if (total >= WINDOW_SIZE + 1) {
            if (lane == 0) wacc += vsum / (float)(total - WINDOW_SIZE);
            if (t == 0)    nvs  += 1;
        }
        if (r + 1 < ROWS_PER_CTA) __syncthreads();  // seg/scnt reuse
    }

    // ---- CTA reduce + one atomic pair per CTA; last CTA finalizes ----
    if (lane == 0) wpart[wid] = wacc;
    __syncthreads();
    if (t == 0) {
        const double acc = (double)wpart[0] + (double)wpart[1]
                         + (double)wpart[2] + (double)wpart[3];
        if (nvs) {
            atomicAdd(&g_total, acc);
            atomicAdd(&g_nvs, nvs);
        }
        __threadfence();
        const unsigned ticket = atomicAdd(&g_counter, 1u);
        if (ticket == (unsigned)(n_ctas - 1)) {
            const double tot = *((volatile double*)&g_total);
            const int    tn  = *((volatile int*)&g_nvs);
            out[0] = (tn > 0) ? (float)(PENALTY_SCALE * tot / (double)tn) : 0.0f;
            g_total = 0.0;
            g_nvs   = 0;
            __threadfence();
            g_counter = 0u;
        }
    }
}

extern "C" void kernel_launch(void* const* d_in, const int* in_sizes, int n_in,
                              void* d_out, int out_size) {
    const int* in = (const int*)d_in[0];
    const int B = in_sizes[0] / ROW_LEN;            // 2048 rows
    const int n_ctas = B / ROWS_PER_CTA;            // 1024 CTAs — one wave
    reach_loss_halo<<<n_ctas, NTHREADS>>>(in, (float*)d_out, n_ctas);
}